// round 2
// baseline (speedup 1.0000x reference)
#include <cuda_runtime.h>

#define NN 100000
#define EE 1600000
#define DD 128

// ---------------- static device scratch (no allocations allowed) ----------------
__device__ int   g_outdeg[NN];
__device__ int   g_indeg[NN];
__device__ float g_nsrc[NN];
__device__ float g_ndst[NN];
__device__ int   g_off[NN + 1];
__device__ int   g_cur[NN];
__device__ int   g_esrc[EE];
__device__ float g_ew[EE];
__device__ float g_agg[(size_t)NN * DD];
__device__ float g_h1[(size_t)NN * DD];

// ---------------- setup kernels ----------------
__global__ void zero_deg_kernel(int n) {
    int i = blockIdx.x * blockDim.x + threadIdx.x;
    if (i < n) { g_outdeg[i] = 0; g_indeg[i] = 0; }
}

__global__ void count_deg_kernel(const int* __restrict__ src,
                                 const int* __restrict__ dst, int E, int n) {
    int e = blockIdx.x * blockDim.x + threadIdx.x;
    if (e < E) {
        int s = src[e];
        int d = dst[e];
        if ((unsigned)s < (unsigned)n) atomicAdd(&g_outdeg[s], 1);
        if ((unsigned)d < (unsigned)n) atomicAdd(&g_indeg[d], 1);
    }
}

__global__ void norm_kernel(int n) {
    int i = blockIdx.x * blockDim.x + threadIdx.x;
    if (i < n) {
        g_nsrc[i] = rsqrtf(fmaxf((float)g_outdeg[i], 1.0f));
        g_ndst[i] = rsqrtf(fmaxf((float)g_indeg[i], 1.0f));
    }
}

// single-block exclusive scan of g_indeg -> g_off
__global__ void scan_kernel(int n, int E) {
    __shared__ int sdata[1024];
    __shared__ int carry;
    int tid = threadIdx.x;
    if (tid == 0) carry = 0;
    __syncthreads();
    for (int base = 0; base < n; base += 1024) {
        int i = base + tid;
        int v = (i < n) ? g_indeg[i] : 0;
        sdata[tid] = v;
        __syncthreads();
        #pragma unroll
        for (int off = 1; off < 1024; off <<= 1) {
            int t = 0;
            if (tid >= off) t = sdata[tid - off];
            __syncthreads();
            sdata[tid] += t;
            __syncthreads();
        }
        int incl = sdata[tid];
        if (i < n) g_off[i] = carry + incl - v;  // exclusive
        __syncthreads();
        if (tid == 0) carry += sdata[1023];
        __syncthreads();
    }
    if (tid == 0) g_off[n] = carry;   // == E when all indices in range
}

__global__ void init_cursor_kernel(int n) {
    int i = blockIdx.x * blockDim.x + threadIdx.x;
    if (i < n) g_cur[i] = g_off[i];
}

__global__ void fill_csr_kernel(const int* __restrict__ src,
                                const int* __restrict__ dst, int E, int n) {
    int e = blockIdx.x * blockDim.x + threadIdx.x;
    if (e < E) {
        int s = src[e];
        int d = dst[e];
        if ((unsigned)s < (unsigned)n && (unsigned)d < (unsigned)n) {
            int pos = atomicAdd(&g_cur[d], 1);
            g_esrc[pos] = s;
            g_ew[pos] = g_nsrc[s];
        }
    }
}

// ---------------- pull-based SpMM: one warp per dst node ----------------
__global__ __launch_bounds__(256)
void spmm_kernel(const float* __restrict__ h, float* __restrict__ agg, int n) {
    int gw = (blockIdx.x * blockDim.x + threadIdx.x) >> 5;
    if (gw >= n) return;
    int lane = threadIdx.x & 31;
    int beg = g_off[gw];
    int end = g_off[gw + 1];
    const float4* hp = (const float4*)h;
    float4 acc = make_float4(0.f, 0.f, 0.f, 0.f);
    int e = beg;
    for (; e + 1 < end; e += 2) {
        int u0 = g_esrc[e];
        int u1 = g_esrc[e + 1];
        float s0 = g_ew[e];
        float s1 = g_ew[e + 1];
        float4 v0 = hp[(size_t)u0 * 32 + lane];
        float4 v1 = hp[(size_t)u1 * 32 + lane];
        acc.x += s0 * v0.x + s1 * v1.x;
        acc.y += s0 * v0.y + s1 * v1.y;
        acc.z += s0 * v0.z + s1 * v1.z;
        acc.w += s0 * v0.w + s1 * v1.w;
    }
    if (e < end) {
        int u0 = g_esrc[e];
        float s0 = g_ew[e];
        float4 v0 = hp[(size_t)u0 * 32 + lane];
        acc.x += s0 * v0.x;
        acc.y += s0 * v0.y;
        acc.z += s0 * v0.z;
        acc.w += s0 * v0.w;
    }
    float nd = g_ndst[gw];
    float4 o = make_float4(acc.x * nd, acc.y * nd, acc.z * nd, acc.w * nd);
    ((float4*)agg)[(size_t)gw * 32 + lane] = o;
}

// ---------------- fp32 GEMM + bias + relu: C[N,128] = relu(A[N,128] @ W[128,128] + b) ----------------
__global__ __launch_bounds__(256, 2)
void gemm_bias_relu_kernel(const float* __restrict__ A, const float* __restrict__ W,
                           const float* __restrict__ bias, float* __restrict__ C, int n) {
    __shared__ float As[16][132];   // padded to kill bank conflicts on transpose-store
    __shared__ float Ws[16][128];
    int tid = threadIdx.x;
    int row0 = blockIdx.x * 128;
    int tx = tid & 15;      // col group: cols tx*8 .. tx*8+7
    int ty = tid >> 4;      // row group: rows ty*8 .. ty*8+7

    float acc[8][8];
    #pragma unroll
    for (int i = 0; i < 8; i++)
        #pragma unroll
        for (int j = 0; j < 8; j++) acc[i][j] = 0.f;

    for (int k0 = 0; k0 < DD; k0 += 16) {
        #pragma unroll
        for (int t = 0; t < 2; t++) {
            int f4 = tid * 2 + t;       // 0..511
            int m  = f4 >> 2;           // 0..127
            int kq = f4 & 3;            // 0..3
            float4 v = make_float4(0.f, 0.f, 0.f, 0.f);
            int r = row0 + m;
            if (r < n) v = *(const float4*)(A + (size_t)r * DD + k0 + kq * 4);
            As[kq * 4 + 0][m] = v.x;
            As[kq * 4 + 1][m] = v.y;
            As[kq * 4 + 2][m] = v.z;
            As[kq * 4 + 3][m] = v.w;
        }
        #pragma unroll
        for (int t = 0; t < 2; t++) {
            int f4 = tid * 2 + t;       // 0..511
            int kk = f4 >> 5;           // 0..15
            int nq = f4 & 31;           // 0..31
            float4 v = *(const float4*)(W + (size_t)(k0 + kk) * DD + nq * 4);
            *(float4*)&Ws[kk][nq * 4] = v;
        }
        __syncthreads();
        #pragma unroll
        for (int kk = 0; kk < 16; kk++) {
            float a[8];
            #pragma unroll
            for (int i = 0; i < 8; i++) a[i] = As[kk][ty * 8 + i];
            float4 w0 = *(float4*)&Ws[kk][tx * 8];
            float4 w1 = *(float4*)&Ws[kk][tx * 8 + 4];
            float w[8] = {w0.x, w0.y, w0.z, w0.w, w1.x, w1.y, w1.z, w1.w};
            #pragma unroll
            for (int i = 0; i < 8; i++)
                #pragma unroll
                for (int j = 0; j < 8; j++)
                    acc[i][j] = fmaf(a[i], w[j], acc[i][j]);
        }
        __syncthreads();
    }

    float bv[8];
    #pragma unroll
    for (int j = 0; j < 8; j++) bv[j] = bias[tx * 8 + j];
    #pragma unroll
    for (int i = 0; i < 8; i++) {
        int r = row0 + ty * 8 + i;
        if (r < n) {
            float4 o0, o1;
            o0.x = fmaxf(acc[i][0] + bv[0], 0.f);
            o0.y = fmaxf(acc[i][1] + bv[1], 0.f);
            o0.z = fmaxf(acc[i][2] + bv[2], 0.f);
            o0.w = fmaxf(acc[i][3] + bv[3], 0.f);
            o1.x = fmaxf(acc[i][4] + bv[4], 0.f);
            o1.y = fmaxf(acc[i][5] + bv[5], 0.f);
            o1.z = fmaxf(acc[i][6] + bv[6], 0.f);
            o1.w = fmaxf(acc[i][7] + bv[7], 0.f);
            *(float4*)(C + (size_t)r * DD + tx * 8)     = o0;
            *(float4*)(C + (size_t)r * DD + tx * 8 + 4) = o1;
        }
    }
}

// ---------------- launch ----------------
extern "C" void kernel_launch(void* const* d_in, const int* in_sizes, int n_in,
                              void* d_out, int out_size) {
    const float* features = (const float*)d_in[0];
    const int*   src      = (const int*)d_in[1];   // jnp.int64 downgrades to int32 (x64 off)
    const int*   dst      = (const int*)d_in[2];
    const float* W1       = (const float*)d_in[3];
    const float* b1       = (const float*)d_in[4];
    const float* W2       = (const float*)d_in[5];
    const float* b2       = (const float*)d_in[6];
    float*       out      = (float*)d_out;

    int n = in_sizes[0] / DD;   // 100000
    int E = in_sizes[1];        // 1600000

    float *agg, *h1;
    cudaGetSymbolAddress((void**)&agg, g_agg);
    cudaGetSymbolAddress((void**)&h1, g_h1);

    int tb = 256;
    int gN = (n + tb - 1) / tb;
    int gE = (E + tb - 1) / tb;
    int gSp = ((n * 32) + tb - 1) / tb;
    int gGemm = (n + 127) / 128;

    zero_deg_kernel<<<gN, tb>>>(n);
    count_deg_kernel<<<gE, tb>>>(src, dst, E, n);
    norm_kernel<<<gN, tb>>>(n);
    scan_kernel<<<1, 1024>>>(n, E);
    init_cursor_kernel<<<gN, tb>>>(n);
    fill_csr_kernel<<<gE, tb>>>(src, dst, E, n);

    // layer 1
    spmm_kernel<<<gSp, tb>>>(features, agg, n);
    gemm_bias_relu_kernel<<<gGemm, tb>>>(agg, W1, b1, h1, n);
    // layer 2
    spmm_kernel<<<gSp, tb>>>(h1, agg, n);
    gemm_bias_relu_kernel<<<gGemm, tb>>>(agg, W2, b2, out, n);
}

// round 3
// speedup vs baseline: 1.3415x; 1.3415x over previous
#include <cuda_runtime.h>

#define NN 100000
#define EE 1600000
#define DD 128
#define SCAN_CHUNK 1024
#define SCAN_B ((NN + SCAN_CHUNK - 1) / SCAN_CHUNK)   // 98

// ---------------- static device scratch (no allocations allowed) ----------------
__device__ int   g_outdeg[NN];
__device__ int   g_indeg[NN];
__device__ float g_nsrc[NN];
__device__ float g_ndst[NN];
__device__ int   g_off[NN + 1];
__device__ int   g_cur[NN];
__device__ int   g_part[SCAN_B + 1];
__device__ int   g_esrc[EE];
__device__ float g_ew[EE];
__device__ float g_agg[(size_t)NN * DD];
__device__ float g_h1[(size_t)NN * DD];

// ---------------- setup kernels ----------------
__global__ void zero_deg_kernel(int n) {
    int i = blockIdx.x * blockDim.x + threadIdx.x;
    if (i < n) { g_outdeg[i] = 0; g_indeg[i] = 0; }
}

__global__ void count_deg_kernel(const int* __restrict__ src,
                                 const int* __restrict__ dst, int E, int n) {
    int e = blockIdx.x * blockDim.x + threadIdx.x;
    if (e < E) {
        int s = src[e];
        int d = dst[e];
        if ((unsigned)s < (unsigned)n) atomicAdd(&g_outdeg[s], 1);
        if ((unsigned)d < (unsigned)n) atomicAdd(&g_indeg[d], 1);
    }
}

__global__ void norm_kernel(int n) {
    int i = blockIdx.x * blockDim.x + threadIdx.x;
    if (i < n) {
        g_nsrc[i] = rsqrtf(fmaxf((float)g_outdeg[i], 1.0f));
        g_ndst[i] = rsqrtf(fmaxf((float)g_indeg[i], 1.0f));
    }
}

// ---- 3-pass grid scan of g_indeg -> g_off (exclusive), fused cursor init ----
// pass 1: per-block (1024-elem chunk) sum -> g_part[b]
__global__ __launch_bounds__(256)
void scan_reduce_kernel(int n) {
    __shared__ int wsum[8];
    int b = blockIdx.x;
    int tid = threadIdx.x;
    int idx = b * SCAN_CHUNK + tid * 4;
    int s = 0;
    #pragma unroll
    for (int t = 0; t < 4; t++)
        if (idx + t < n) s += g_indeg[idx + t];
    #pragma unroll
    for (int o = 16; o > 0; o >>= 1) s += __shfl_down_sync(0xffffffffu, s, o);
    int lane = tid & 31, wid = tid >> 5;
    if (lane == 0) wsum[wid] = s;
    __syncthreads();
    if (tid == 0) {
        int t = 0;
        #pragma unroll
        for (int w = 0; w < 8; w++) t += wsum[w];
        g_part[b] = t;
    }
}

// pass 2: single block exclusive scan of g_part[0..B)
__global__ __launch_bounds__(128)
void scan_partials_kernel(int B, int E) {
    __shared__ int sdata[128];
    int tid = threadIdx.x;
    int v = (tid < B) ? g_part[tid] : 0;
    sdata[tid] = v;
    __syncthreads();
    #pragma unroll
    for (int o = 1; o < 128; o <<= 1) {
        int t = (tid >= o) ? sdata[tid - o] : 0;
        __syncthreads();
        sdata[tid] += t;
        __syncthreads();
    }
    if (tid < B) g_part[tid] = sdata[tid] - v;   // exclusive
    if (tid == 0) g_off[NN] = E;
}

// pass 3: per-block downsweep: exclusive scan of chunk + g_part[b] -> g_off, g_cur
__global__ __launch_bounds__(256)
void scan_down_kernel(int n) {
    __shared__ int wscan[8];
    int b = blockIdx.x;
    int tid = threadIdx.x;
    int lane = tid & 31, wid = tid >> 5;
    int idx = b * SCAN_CHUNK + tid * 4;
    int v0 = 0, v1 = 0, v2 = 0, v3 = 0;
    if (idx + 0 < n) v0 = g_indeg[idx + 0];
    if (idx + 1 < n) v1 = g_indeg[idx + 1];
    if (idx + 2 < n) v2 = g_indeg[idx + 2];
    if (idx + 3 < n) v3 = g_indeg[idx + 3];
    int tsum = v0 + v1 + v2 + v3;
    // inclusive warp scan of tsum
    int x = tsum;
    #pragma unroll
    for (int o = 1; o < 32; o <<= 1) {
        int y = __shfl_up_sync(0xffffffffu, x, o);
        if (lane >= o) x += y;
    }
    if (lane == 31) wscan[wid] = x;
    __syncthreads();
    if (wid == 0 && lane < 8) {
        int s = wscan[lane];
        #pragma unroll
        for (int o = 1; o < 8; o <<= 1) {
            int y = __shfl_up_sync(0x000000ffu, s, o);
            if (lane >= o) s += y;
        }
        wscan[lane] = s;   // inclusive over warps
    }
    __syncthreads();
    int base = g_part[b] + (wid ? wscan[wid - 1] : 0) + (x - tsum);
    if (idx + 0 < n) { g_off[idx + 0] = base;            g_cur[idx + 0] = base; }
    if (idx + 1 < n) { g_off[idx + 1] = base + v0;       g_cur[idx + 1] = base + v0; }
    if (idx + 2 < n) { int t = base + v0 + v1;  g_off[idx + 2] = t; g_cur[idx + 2] = t; }
    if (idx + 3 < n) { int t = base + v0 + v1 + v2; g_off[idx + 3] = t; g_cur[idx + 3] = t; }
}

__global__ void fill_csr_kernel(const int* __restrict__ src,
                                const int* __restrict__ dst, int E, int n) {
    int e = blockIdx.x * blockDim.x + threadIdx.x;
    if (e < E) {
        int s = src[e];
        int d = dst[e];
        if ((unsigned)s < (unsigned)n && (unsigned)d < (unsigned)n) {
            int pos = atomicAdd(&g_cur[d], 1);
            g_esrc[pos] = s;
            g_ew[pos] = g_nsrc[s];
        }
    }
}

// ---------------- pull-based SpMM: one warp per dst node ----------------
__global__ __launch_bounds__(256)
void spmm_kernel(const float* __restrict__ h, float* __restrict__ agg, int n) {
    int gw = (blockIdx.x * blockDim.x + threadIdx.x) >> 5;
    if (gw >= n) return;
    int lane = threadIdx.x & 31;
    int beg = g_off[gw];
    int end = g_off[gw + 1];
    const float4* hp = (const float4*)h;
    float4 acc = make_float4(0.f, 0.f, 0.f, 0.f);
    int e = beg;
    for (; e + 1 < end; e += 2) {
        int u0 = g_esrc[e];
        int u1 = g_esrc[e + 1];
        float s0 = g_ew[e];
        float s1 = g_ew[e + 1];
        float4 v0 = hp[(size_t)u0 * 32 + lane];
        float4 v1 = hp[(size_t)u1 * 32 + lane];
        acc.x += s0 * v0.x + s1 * v1.x;
        acc.y += s0 * v0.y + s1 * v1.y;
        acc.z += s0 * v0.z + s1 * v1.z;
        acc.w += s0 * v0.w + s1 * v1.w;
    }
    if (e < end) {
        int u0 = g_esrc[e];
        float s0 = g_ew[e];
        float4 v0 = hp[(size_t)u0 * 32 + lane];
        acc.x += s0 * v0.x;
        acc.y += s0 * v0.y;
        acc.z += s0 * v0.z;
        acc.w += s0 * v0.w;
    }
    float nd = g_ndst[gw];
    float4 o = make_float4(acc.x * nd, acc.y * nd, acc.z * nd, acc.w * nd);
    ((float4*)agg)[(size_t)gw * 32 + lane] = o;
}

// ---------------- fp32 GEMM + bias + relu: C[N,128] = relu(A[N,128] @ W[128,128] + b) ----------------
__global__ __launch_bounds__(256, 2)
void gemm_bias_relu_kernel(const float* __restrict__ A, const float* __restrict__ W,
                           const float* __restrict__ bias, float* __restrict__ C, int n) {
    __shared__ float As[16][132];
    __shared__ float Ws[16][128];
    int tid = threadIdx.x;
    int row0 = blockIdx.x * 128;
    int tx = tid & 15;
    int ty = tid >> 4;

    float acc[8][8];
    #pragma unroll
    for (int i = 0; i < 8; i++)
        #pragma unroll
        for (int j = 0; j < 8; j++) acc[i][j] = 0.f;

    for (int k0 = 0; k0 < DD; k0 += 16) {
        #pragma unroll
        for (int t = 0; t < 2; t++) {
            int f4 = tid * 2 + t;
            int m  = f4 >> 2;
            int kq = f4 & 3;
            float4 v = make_float4(0.f, 0.f, 0.f, 0.f);
            int r = row0 + m;
            if (r < n) v = *(const float4*)(A + (size_t)r * DD + k0 + kq * 4);
            As[kq * 4 + 0][m] = v.x;
            As[kq * 4 + 1][m] = v.y;
            As[kq * 4 + 2][m] = v.z;
            As[kq * 4 + 3][m] = v.w;
        }
        #pragma unroll
        for (int t = 0; t < 2; t++) {
            int f4 = tid * 2 + t;
            int kk = f4 >> 5;
            int nq = f4 & 31;
            float4 v = *(const float4*)(W + (size_t)(k0 + kk) * DD + nq * 4);
            *(float4*)&Ws[kk][nq * 4] = v;
        }
        __syncthreads();
        #pragma unroll
        for (int kk = 0; kk < 16; kk++) {
            float a[8];
            #pragma unroll
            for (int i = 0; i < 8; i++) a[i] = As[kk][ty * 8 + i];
            float4 w0 = *(float4*)&Ws[kk][tx * 8];
            float4 w1 = *(float4*)&Ws[kk][tx * 8 + 4];
            float w[8] = {w0.x, w0.y, w0.z, w0.w, w1.x, w1.y, w1.z, w1.w};
            #pragma unroll
            for (int i = 0; i < 8; i++)
                #pragma unroll
                for (int j = 0; j < 8; j++)
                    acc[i][j] = fmaf(a[i], w[j], acc[i][j]);
        }
        __syncthreads();
    }

    float bv[8];
    #pragma unroll
    for (int j = 0; j < 8; j++) bv[j] = bias[tx * 8 + j];
    #pragma unroll
    for (int i = 0; i < 8; i++) {
        int r = row0 + ty * 8 + i;
        if (r < n) {
            float4 o0, o1;
            o0.x = fmaxf(acc[i][0] + bv[0], 0.f);
            o0.y = fmaxf(acc[i][1] + bv[1], 0.f);
            o0.z = fmaxf(acc[i][2] + bv[2], 0.f);
            o0.w = fmaxf(acc[i][3] + bv[3], 0.f);
            o1.x = fmaxf(acc[i][4] + bv[4], 0.f);
            o1.y = fmaxf(acc[i][5] + bv[5], 0.f);
            o1.z = fmaxf(acc[i][6] + bv[6], 0.f);
            o1.w = fmaxf(acc[i][7] + bv[7], 0.f);
            *(float4*)(C + (size_t)r * DD + tx * 8)     = o0;
            *(float4*)(C + (size_t)r * DD + tx * 8 + 4) = o1;
        }
    }
}

// ---------------- launch ----------------
extern "C" void kernel_launch(void* const* d_in, const int* in_sizes, int n_in,
                              void* d_out, int out_size) {
    const float* features = (const float*)d_in[0];
    const int*   src      = (const int*)d_in[1];   // jnp.int64 downgrades to int32 (x64 off)
    const int*   dst      = (const int*)d_in[2];
    const float* W1       = (const float*)d_in[3];
    const float* b1       = (const float*)d_in[4];
    const float* W2       = (const float*)d_in[5];
    const float* b2       = (const float*)d_in[6];
    float*       out      = (float*)d_out;

    int n = in_sizes[0] / DD;   // 100000
    int E = in_sizes[1];        // 1600000

    float *agg, *h1;
    cudaGetSymbolAddress((void**)&agg, g_agg);
    cudaGetSymbolAddress((void**)&h1, g_h1);

    int tb = 256;
    int gN = (n + tb - 1) / tb;
    int gE = (E + tb - 1) / tb;
    int gSp = ((n * 32) + tb - 1) / tb;
    int gGemm = (n + 127) / 128;
    int B = (n + SCAN_CHUNK - 1) / SCAN_CHUNK;

    zero_deg_kernel<<<gN, tb>>>(n);
    count_deg_kernel<<<gE, tb>>>(src, dst, E, n);
    norm_kernel<<<gN, tb>>>(n);
    scan_reduce_kernel<<<B, 256>>>(n);
    scan_partials_kernel<<<1, 128>>>(B, E);
    scan_down_kernel<<<B, 256>>>(n);
    fill_csr_kernel<<<gE, tb>>>(src, dst, E, n);

    // layer 1
    spmm_kernel<<<gSp, tb>>>(features, agg, n);
    gemm_bias_relu_kernel<<<gGemm, tb>>>(agg, W1, b1, h1, n);
    // layer 2
    spmm_kernel<<<gSp, tb>>>(h1, agg, n);
    gemm_bias_relu_kernel<<<gGemm, tb>>>(agg, W2, b2, out, n);
}